// round 11
// baseline (speedup 1.0000x reference)
#include <cuda_runtime.h>

// Split-pipeline GNN:
//   K1 enc:  x -> h           (thread = 2 same-type nodes)
//   K2 msg:  h -> z = h+agg   (thread = 1 graph; lin_k weights in smem)
//   K3 mlp:  z -> h' = relu(LN(MLP(z)))  (thread = 3 nodes, NV=3 weight reuse)
//   K4 fc:   h -> out         (warp groups of 4 lanes = nodes, 2 graphs/lane)
// Sequence: K1; K2(lin1); K3(m1); K2(lin2); K3(m2); K4.  All f32, packed f32x2 FMA.

typedef unsigned long long u64;

#define MAXN 1000064
__device__ float g_hb[(size_t)MAXN * 16];
__device__ float g_zb[(size_t)MAXN * 16];

// ---- packed f32x2 helpers ----
__device__ __forceinline__ u64 pk(float lo, float hi) {
    u64 r; asm("mov.b64 %0,{%1,%2};" : "=l"(r) : "f"(lo), "f"(hi)); return r;
}
__device__ __forceinline__ void up(u64 v, float& lo, float& hi) {
    asm("mov.b64 {%0,%1},%2;" : "=f"(lo), "=f"(hi) : "l"(v));
}
__device__ __forceinline__ u64 f2(u64 a, u64 b, u64 c) {
    u64 d; asm("fma.rn.f32x2 %0,%1,%2,%3;" : "=l"(d) : "l"(a), "l"(b), "l"(c)); return d;
}
__device__ __forceinline__ u64 a2(u64 a, u64 b) {
    u64 d; asm("add.rn.f32x2 %0,%1,%2;" : "=l"(d) : "l"(a), "l"(b)); return d;
}
__device__ __forceinline__ u64 r2(u64 a) {
    float l, h; up(a, l, h);
    return pk(fmaxf(l, 0.f), fmaxf(h, 0.f));
}
__device__ __forceinline__ ulonglong2 ld2(const float* p) {
    return *reinterpret_cast<const ulonglong2*>(p);
}

// ============================ K1: encoder ============================
struct EncP { const float* x; const float* w[8]; float* hout; int N; };

__global__ void __launch_bounds__(256, 2) k_enc(EncP p)
{
    __shared__ float S[736];
    // je_w1(80) je_b1(16) je_w2(256) je_b2(16) mu_w1(80) mu_b1(16) mu_w2(256) mu_b2(16)
    {
        const int sz[8]  = {80,16,256,16,80,16,256,16};
        const int off[8] = {0,80,96,352,368,448,464,720};
        for (int a = 0; a < 8; a++)
            for (int i = threadIdx.x; i < sz[a]; i += 256) S[off[a] + i] = p.w[a][i];
    }
    __syncthreads();

    int half = p.N >> 1;
    int t = blockIdx.x * 256 + threadIdx.x;
    if (t >= half) return;
    int n0 = t, n1 = t + half;          // half % 4 == 0 -> same node type
    int node = t & 3;

    const float* w1p = (node == 3) ? (S + 368) : (S + 0);
    const float* b1p = (node == 3) ? (S + 448) : (S + 80);
    const float* w2p = (node == 3) ? (S + 464) : (S + 96);
    const float* b2p = (node == 3) ? (S + 720) : (S + 352);

    float xin[2][5];
#pragma unroll
    for (int k = 0; k < 5; k++) {
        xin[0][k] = __ldg(p.x + (long long)n0 * 5 + k);
        xin[1][k] = __ldg(p.x + (long long)n1 * 5 + k);
    }

    u64 tv[2][8];
    {
        ulonglong2 a = ld2(b1p), b = ld2(b1p+4), c = ld2(b1p+8), d = ld2(b1p+12);
#pragma unroll
        for (int nv = 0; nv < 2; nv++) {
            tv[nv][0]=a.x; tv[nv][1]=a.y; tv[nv][2]=b.x; tv[nv][3]=b.y;
            tv[nv][4]=c.x; tv[nv][5]=c.y; tv[nv][6]=d.x; tv[nv][7]=d.y;
        }
    }
#pragma unroll
    for (int k = 0; k < 5; k++) {
        const float* r = w1p + k * 16;
        ulonglong2 a = ld2(r), b = ld2(r+4), c = ld2(r+8), d = ld2(r+12);
        u64 wv[8] = {a.x,a.y,b.x,b.y,c.x,c.y,d.x,d.y};
#pragma unroll
        for (int nv = 0; nv < 2; nv++) {
            u64 xp = pk(xin[nv][k], xin[nv][k]);
#pragma unroll
            for (int j = 0; j < 8; j++) tv[nv][j] = f2(xp, wv[j], tv[nv][j]);
        }
    }

    u64 h[2][8];
    {
        ulonglong2 a = ld2(b2p), b = ld2(b2p+4), c = ld2(b2p+8), d = ld2(b2p+12);
#pragma unroll
        for (int nv = 0; nv < 2; nv++) {
            h[nv][0]=a.x; h[nv][1]=a.y; h[nv][2]=b.x; h[nv][3]=b.y;
            h[nv][4]=c.x; h[nv][5]=c.y; h[nv][6]=d.x; h[nv][7]=d.y;
        }
    }
#pragma unroll
    for (int jp = 0; jp < 8; jp++) {
        u64 xlo[2], xhi[2];
#pragma unroll
        for (int nv = 0; nv < 2; nv++) {
            float a, b; up(tv[nv][jp], a, b);
            a = fmaxf(a, 0.f); b = fmaxf(b, 0.f);
            xlo[nv] = pk(a, a); xhi[nv] = pk(b, b);
        }
#pragma unroll
        for (int tt = 0; tt < 2; tt++) {
            const float* r = w2p + (2 * jp + tt) * 16;
            ulonglong2 a = ld2(r), b = ld2(r+4), c = ld2(r+8), d = ld2(r+12);
            u64 wv[8] = {a.x,a.y,b.x,b.y,c.x,c.y,d.x,d.y};
#pragma unroll
            for (int nv = 0; nv < 2; nv++) {
                u64 xp = tt ? xhi[nv] : xlo[nv];
#pragma unroll
                for (int j = 0; j < 8; j++) h[nv][j] = f2(xp, wv[j], h[nv][j]);
            }
        }
    }

    int nn[2] = {n0, n1};
#pragma unroll
    for (int nv = 0; nv < 2; nv++) {
        float* dst = p.hout + (long long)nn[nv] * 16;
#pragma unroll
        for (int q = 0; q < 4; q++) {
            ulonglong2 v; v.x = h[nv][2*q]; v.y = h[nv][2*q+1];
            *reinterpret_cast<ulonglong2*>(dst + 4 * q) = v;
        }
    }
}

// ============================ K2: message ============================
struct MsgP { const float* hin; const float* ea; const float* lw; const float* lb;
              float* zout; int G; };

__global__ void __launch_bounds__(256, 2) k_msg(MsgP p)
{
    __shared__ float S[80];   // lw 64 | lb 16
    for (int i = threadIdx.x; i < 64; i += 256) S[i] = p.lw[i];
    for (int i = threadIdx.x; i < 16; i += 256) S[64 + i] = p.lb[i];
    __syncthreads();

    int g = blockIdx.x * 256 + threadIdx.x;
    if (g >= p.G) return;

    float ef[12][4];
    {
        const float4* eb = reinterpret_cast<const float4*>(p.ea + (long long)g * 48);
#pragma unroll
        for (int e = 0; e < 12; e++) {
            float4 v = __ldg(eb + e);
            ef[e][0]=v.x; ef[e][1]=v.y; ef[e][2]=v.z; ef[e][3]=v.w;
        }
    }

    const float* hrow = p.hin + (long long)g * 64;
    float* zrow = p.zout + (long long)g * 64;

#pragma unroll
    for (int v = 0; v < 4; v++) {
        ulonglong2 bb = ld2(S + 64 + 4 * v);
        u64 wk0[4], wk1[4];
#pragma unroll
        for (int k = 0; k < 4; k++) {
            ulonglong2 w = ld2(S + k * 16 + 4 * v);
            wk0[k] = w.x; wk1[k] = w.y;
        }
        u64 hv0[4], hv1[4];
#pragma unroll
        for (int n = 0; n < 4; n++) {
            ulonglong2 hc = *reinterpret_cast<const ulonglong2*>(hrow + n * 16 + 4 * v);
            hv0[n] = hc.x; hv1[n] = hc.y;
        }
#pragma unroll
        for (int tgt = 0; tgt < 4; tgt++) {
            u64 agg0 = 0ull, agg1 = 0ull;
#pragma unroll
            for (int s = 1; s < 4; s++) {
                int src = (tgt + s) & 3;
                int e = src * 3 + tgt - (tgt > src ? 1 : 0);
                u64 m0 = bb.x, m1 = bb.y;
#pragma unroll
                for (int k = 0; k < 4; k++) {
                    u64 ep = pk(ef[e][k], ef[e][k]);
                    m0 = f2(ep, wk0[k], m0);
                    m1 = f2(ep, wk1[k], m1);
                }
                agg0 = a2(agg0, r2(a2(m0, hv0[src])));
                agg1 = a2(agg1, r2(a2(m1, hv1[src])));
            }
            ulonglong2 z;
            z.x = a2(hv0[tgt], agg0);
            z.y = a2(hv1[tgt], agg1);
            *reinterpret_cast<ulonglong2*>(zrow + tgt * 16 + 4 * v) = z;
        }
    }
}

// ============================ K3: MLP + LN + relu ============================
struct MlpP { const float* zin; const float* w1; const float* b1;
              const float* w2; const float* b2; float* hout; int N; };

__global__ void __launch_bounds__(160, 3) k_mlp(MlpP p)
{
    __shared__ float S[2128];  // w1 1024 | b1 64 | w2 1024 | b2 16
    for (int i = threadIdx.x; i < 1024; i += 160) S[i] = p.w1[i];
    for (int i = threadIdx.x; i < 64;   i += 160) S[1024 + i] = p.b1[i];
    for (int i = threadIdx.x; i < 1024; i += 160) S[1088 + i] = p.w2[i];
    for (int i = threadIdx.x; i < 16;   i += 160) S[2112 + i] = p.b2[i];
    __syncthreads();
    const float* w1 = S;
    const float* b1 = S + 1024;
    const float* w2 = S + 1088;
    const float* b2 = S + 2112;

    int Sn = (p.N + 2) / 3;
    int t = blockIdx.x * 160 + threadIdx.x;
    if (t >= Sn) return;

    int n[3]; bool valid[3];
#pragma unroll
    for (int q = 0; q < 3; q++) {
        n[q] = t + q * Sn;
        valid[q] = n[q] < p.N;
        if (!valid[q]) n[q] = 0;
    }

    u64 in[3][8];
#pragma unroll
    for (int q = 0; q < 3; q++) {
        const float* zr = p.zin + (long long)n[q] * 16;
#pragma unroll
        for (int c4 = 0; c4 < 4; c4++) {
            ulonglong2 v = *reinterpret_cast<const ulonglong2*>(zr + 4 * c4);
            in[q][2*c4] = v.x; in[q][2*c4+1] = v.y;
        }
    }

    u64 out[3][8];
    {
        ulonglong2 a = ld2(b2), b = ld2(b2+4), c = ld2(b2+8), d = ld2(b2+12);
#pragma unroll
        for (int q = 0; q < 3; q++) {
            out[q][0]=a.x; out[q][1]=a.y; out[q][2]=b.x; out[q][3]=b.y;
            out[q][4]=c.x; out[q][5]=c.y; out[q][6]=d.x; out[q][7]=d.y;
        }
    }

#pragma unroll
    for (int c = 0; c < 8; c++) {
        u64 hid[3][4];
        {
            ulonglong2 a = ld2(b1 + c * 8), b = ld2(b1 + c * 8 + 4);
#pragma unroll
            for (int q = 0; q < 3; q++) {
                hid[q][0]=a.x; hid[q][1]=a.y; hid[q][2]=b.x; hid[q][3]=b.y;
            }
        }
#pragma unroll
        for (int jp = 0; jp < 8; jp++) {
            u64 xlo[3], xhi[3];
#pragma unroll
            for (int q = 0; q < 3; q++) {
                float a, b; up(in[q][jp], a, b);
                xlo[q] = pk(a, a); xhi[q] = pk(b, b);
            }
#pragma unroll
            for (int tt = 0; tt < 2; tt++) {
                const float* r = w1 + (2 * jp + tt) * 64 + c * 8;
                ulonglong2 wa = ld2(r), wb = ld2(r + 4);
                u64 wv[4] = {wa.x, wa.y, wb.x, wb.y};
#pragma unroll
                for (int q = 0; q < 3; q++) {
                    u64 xp = tt ? xhi[q] : xlo[q];
#pragma unroll
                    for (int v = 0; v < 4; v++) hid[q][v] = f2(xp, wv[v], hid[q][v]);
                }
            }
        }
#pragma unroll
        for (int v = 0; v < 4; v++) {
            float s0[3], s1[3];
#pragma unroll
            for (int q = 0; q < 3; q++) {
                float a, b; up(hid[q][v], a, b);
                s0[q] = fmaxf(a, 0.f); s1[q] = fmaxf(b, 0.f);
            }
#pragma unroll
            for (int tt = 0; tt < 2; tt++) {
                int u = c * 8 + 2 * v + tt;
                const float* r = w2 + u * 16;
                ulonglong2 wa = ld2(r), wb = ld2(r+4), wc = ld2(r+8), wd = ld2(r+12);
                u64 wv[8] = {wa.x, wa.y, wb.x, wb.y, wc.x, wc.y, wd.x, wd.y};
#pragma unroll
                for (int q = 0; q < 3; q++) {
                    float s = tt ? s1[q] : s0[q];
                    u64 sp = pk(s, s);
#pragma unroll
                    for (int j = 0; j < 8; j++) out[q][j] = f2(sp, wv[j], out[q][j]);
                }
            }
        }
    }

    // LayerNorm + relu + store
#pragma unroll
    for (int q = 0; q < 3; q++) {
        if (!valid[q]) continue;
        float o[16];
#pragma unroll
        for (int j = 0; j < 8; j++) up(out[q][j], o[2*j], o[2*j+1]);
        float mean = 0.f;
#pragma unroll
        for (int d = 0; d < 16; d++) mean += o[d];
        mean *= (1.f / 16.f);
        float var = 0.f;
#pragma unroll
        for (int d = 0; d < 16; d++) { float dd = o[d] - mean; var = fmaf(dd, dd, var); }
        var *= (1.f / 16.f);
        float inv = rsqrtf(var + 1e-5f);
        float* dst = p.hout + (long long)n[q] * 16;
#pragma unroll
        for (int c4 = 0; c4 < 4; c4++) {
            ulonglong2 vv;
            vv.x = pk(fmaxf((o[4*c4]   - mean) * inv, 0.f),
                      fmaxf((o[4*c4+1] - mean) * inv, 0.f));
            vv.y = pk(fmaxf((o[4*c4+2] - mean) * inv, 0.f),
                      fmaxf((o[4*c4+3] - mean) * inv, 0.f));
            *reinterpret_cast<ulonglong2*>(dst + 4 * c4) = vv;
        }
    }
}

// ============================ K4: pool + FC ============================
struct FcP { const float* h; const float* fw1; const float* fb1;
             const float* fw2; const float* fb2; float* out; int G; };

__global__ void __launch_bounds__(256, 2) k_fc(FcP p)
{
    __shared__ float S[2176];  // fw1 2048 | fb1 64 | fw2 64
    for (int i = threadIdx.x; i < 2048; i += 256) S[i] = p.fw1[i];
    for (int i = threadIdx.x; i < 64;   i += 256) S[2048 + i] = p.fb1[i];
    for (int i = threadIdx.x; i < 64;   i += 256) S[2112 + i] = p.fw2[i];
    __syncthreads();

    int tid = threadIdx.x;
    int lane = tid & 31;
    int node = lane & 3;
    int group = lane >> 2;
    int warpG = (int)((blockIdx.x * 256u + tid) >> 5);
    if (warpG * 16 >= p.G) return;

    int gidx[2], gc[2]; bool valid[2];
#pragma unroll
    for (int nv = 0; nv < 2; nv++) {
        gidx[nv] = warpG * 16 + group + 8 * nv;
        valid[nv] = gidx[nv] < p.G;
        gc[nv] = valid[nv] ? gidx[nv] : (p.G - 1);
    }

    u64 h[2][8];
#pragma unroll
    for (int nv = 0; nv < 2; nv++) {
        const float* hr = p.h + (long long)(gc[nv] * 4 + node) * 16;
#pragma unroll
        for (int c4 = 0; c4 < 4; c4++) {
            ulonglong2 v = *reinterpret_cast<const ulonglong2*>(hr + 4 * c4);
            h[nv][2*c4] = v.x; h[nv][2*c4+1] = v.y;
        }
    }

    float g[2][32];
#pragma unroll
    for (int nv = 0; nv < 2; nv++) {
#pragma unroll
        for (int j = 0; j < 8; j++) {
            u64 s = h[nv][j];
            s = a2(s, __shfl_xor_sync(0xffffffffu, s, 1));
            s = a2(s, __shfl_xor_sync(0xffffffffu, s, 2));
            float sa, sb; up(s, sa, sb);
            g[nv][2*j]   = sa * 0.25f;
            g[nv][2*j+1] = sb * 0.25f;

            u64 mx = h[nv][j];
            u64 o1 = __shfl_xor_sync(0xffffffffu, mx, 1);
            float a0, b0, a1, b1; up(mx, a0, b0); up(o1, a1, b1);
            mx = pk(fmaxf(a0, a1), fmaxf(b0, b1));
            u64 o2 = __shfl_xor_sync(0xffffffffu, mx, 2);
            up(mx, a0, b0); up(o2, a1, b1);
            g[nv][16 + 2*j]   = fmaxf(a0, a1);
            g[nv][16 + 2*j+1] = fmaxf(b0, b1);
        }
        float mean = 0.f;
#pragma unroll
        for (int d = 0; d < 32; d++) mean += g[nv][d];
        mean *= (1.f / 32.f);
        float var = 0.f;
#pragma unroll
        for (int d = 0; d < 32; d++) { float dd = g[nv][d] - mean; var = fmaf(dd, dd, var); }
        var *= (1.f / 32.f);
        float inv = rsqrtf(var + 1e-5f);
#pragma unroll
        for (int d = 0; d < 32; d++) g[nv][d] = (g[nv][d] - mean) * inv;
    }

    u64 av[2][8];
    {
        const float* r = S + 2048 + node * 16;
        ulonglong2 a = ld2(r), b = ld2(r+4), c = ld2(r+8), d = ld2(r+12);
#pragma unroll
        for (int nv = 0; nv < 2; nv++) {
            av[nv][0]=a.x; av[nv][1]=a.y; av[nv][2]=b.x; av[nv][3]=b.y;
            av[nv][4]=c.x; av[nv][5]=c.y; av[nv][6]=d.x; av[nv][7]=d.y;
        }
    }
#pragma unroll
    for (int k = 0; k < 32; k++) {
        const float* r = S + k * 64 + node * 16;
        ulonglong2 wa = ld2(r), wb = ld2(r+4), wc = ld2(r+8), wd = ld2(r+12);
        u64 wv[8] = {wa.x, wa.y, wb.x, wb.y, wc.x, wc.y, wd.x, wd.y};
#pragma unroll
        for (int nv = 0; nv < 2; nv++) {
            u64 gp = pk(g[nv][k], g[nv][k]);
#pragma unroll
            for (int j = 0; j < 8; j++) av[nv][j] = f2(gp, wv[j], av[nv][j]);
        }
    }
    float acc[2] = {0.f, 0.f};
#pragma unroll
    for (int j = 0; j < 8; j++) {
        float2 w2v = *reinterpret_cast<const float2*>(S + 2112 + node * 16 + 2 * j);
#pragma unroll
        for (int nv = 0; nv < 2; nv++) {
            float a, b; up(av[nv][j], a, b);
            acc[nv] = fmaf(fmaxf(a, 0.f), w2v.x, acc[nv]);
            acc[nv] = fmaf(fmaxf(b, 0.f), w2v.y, acc[nv]);
        }
    }
    const float fcb2 = __ldg(p.fb2);
#pragma unroll
    for (int nv = 0; nv < 2; nv++) {
        acc[nv] += __shfl_xor_sync(0xffffffffu, acc[nv], 1);
        acc[nv] += __shfl_xor_sync(0xffffffffu, acc[nv], 2);
        if (node == 0 && valid[nv])
            p.out[gidx[nv]] = acc[nv] + fcb2;
    }
}

// ============================ launch ============================
extern "C" void kernel_launch(void* const* d_in, const int* in_sizes, int n_in,
                              void* d_out, int out_size)
{
    const float* x  = (const float*)d_in[0];
    const float* ea = (const float*)d_in[1];
    const float* w[24];
    for (int i = 0; i < 24; i++) w[i] = (const float*)d_in[2 + i];

    int N = in_sizes[0] / 5;      // nodes
    int G = N / 4;                // graphs
    if (N > MAXN) N = MAXN;

    float* hb; float* zb;
    cudaGetSymbolAddress((void**)&hb, g_hb);
    cudaGetSymbolAddress((void**)&zb, g_zb);

    // K1: encoder
    {
        EncP p; p.x = x; for (int i = 0; i < 8; i++) p.w[i] = w[i];
        p.hout = hb; p.N = N;
        int th = N / 2;
        k_enc<<<(th + 255) / 256, 256>>>(p);
    }
    // K2: msg layer 1
    {
        MsgP p; p.hin = hb; p.ea = ea; p.lw = w[8]; p.lb = w[9];
        p.zout = zb; p.G = G;
        k_msg<<<(G + 255) / 256, 256>>>(p);
    }
    // K3: mlp layer 1
    {
        MlpP p; p.zin = zb; p.w1 = w[10]; p.b1 = w[11]; p.w2 = w[12]; p.b2 = w[13];
        p.hout = hb; p.N = N;
        int Sn = (N + 2) / 3;
        k_mlp<<<(Sn + 159) / 160, 160>>>(p);
    }
    // K2: msg layer 2
    {
        MsgP p; p.hin = hb; p.ea = ea; p.lw = w[14]; p.lb = w[15];
        p.zout = zb; p.G = G;
        k_msg<<<(G + 255) / 256, 256>>>(p);
    }
    // K3: mlp layer 2
    {
        MlpP p; p.zin = zb; p.w1 = w[16]; p.b1 = w[17]; p.w2 = w[18]; p.b2 = w[19];
        p.hout = hb; p.N = N;
        int Sn = (N + 2) / 3;
        k_mlp<<<(Sn + 159) / 160, 160>>>(p);
    }
    // K4: pool + FC
    {
        FcP p; p.h = hb; p.fw1 = w[20]; p.fb1 = w[21]; p.fw2 = w[22]; p.fb2 = w[23];
        p.out = (float*)d_out; p.G = G;
        k_fc<<<(G + 127) / 128, 256>>>(p);
    }
}

// round 12
// speedup vs baseline: 1.6470x; 1.6470x over previous
#include <cuda_runtime.h>

// R7 structure (NV=2, packed f32x2, 256thr x 2 blocks/SM) with warp-uniform
// MLP/lin weights moved to __constant__ memory (filled by a pack kernel via
// the symbol's global address - graph-capturable, no memcpy node).
// Divergent-index weights (encoder, FC) stay in shared memory.

#define NTHREADS 256
#define NV 2

typedef unsigned long long u64;

// ---- constant-memory weights (float4 units) ----
// floats: L1W 0(64) L1B 64(16) M1W1 80(1024) M1B1 1104(64) M1W2 1168(1024)
//         M1B2 2192(16) L2W 2208(64) L2B 2272(16) M2W1 2288(1024)
//         M2B1 3312(64) M2W2 3376(1024) M2B2 4400(16)   total 4416 floats
#define cL1W  0
#define cL1B  16
#define cM1W1 20
#define cM1B1 276
#define cM1W2 292
#define cM1B2 548
#define cL2W  552
#define cL2B  568
#define cM2W1 572
#define cM2B1 828
#define cM2W2 844
#define cM2B2 1100
#define CW_F4 1104

__constant__ float4 CW[CW_F4];

// ---- shared memory layout (floats): encoder + FC (divergent-index) ----
#define JE_W1 0      // 80
#define JE_B1 80     // 16
#define JE_W2 96     // 256
#define JE_B2 352    // 16
#define MU_W1 368    // 80
#define MU_B1 448    // 16
#define MU_W2 464    // 256
#define MU_B2 720    // 16
#define FC_W1 736    // 2048
#define FC_B1 2784   // 64
#define FC_W2 2848   // 64
#define SMEM_FLOATS 2912

struct Params {
    const float* x;
    const float* ea;
    const float* w[24];   // je_w1..fc_b2 in metadata order
    float* out;
    int G;
};

struct PackP { const float* src[12]; float* dst; };

__global__ void pack_kernel(PackP p)
{
    const int sz[12]  = {64,16,1024,64,1024,16, 64,16,1024,64,1024,16};
    const int off[12] = {0,64,80,1104,1168,2192, 2208,2272,2288,3312,3376,4400};
    for (int a = 0; a < 12; a++) {
        const float* s = p.src[a];
        float* d = p.dst + off[a];
        for (int i = threadIdx.x; i < sz[a]; i += blockDim.x) d[i] = s[i];
    }
}

// ---- packed f32x2 helpers ----
__device__ __forceinline__ u64 pk(float lo, float hi) {
    u64 r; asm("mov.b64 %0,{%1,%2};" : "=l"(r) : "f"(lo), "f"(hi)); return r;
}
__device__ __forceinline__ void up(u64 v, float& lo, float& hi) {
    asm("mov.b64 {%0,%1},%2;" : "=f"(lo), "=f"(hi) : "l"(v));
}
__device__ __forceinline__ u64 f2(u64 a, u64 b, u64 c) {
    u64 d; asm("fma.rn.f32x2 %0,%1,%2,%3;" : "=l"(d) : "l"(a), "l"(b), "l"(c)); return d;
}
__device__ __forceinline__ u64 a2(u64 a, u64 b) {
    u64 d; asm("add.rn.f32x2 %0,%1,%2;" : "=l"(d) : "l"(a), "l"(b)); return d;
}
__device__ __forceinline__ u64 r2(u64 a) {
    float l, h; up(a, l, h);
    return pk(fmaxf(l, 0.f), fmaxf(h, 0.f));
}
__device__ __forceinline__ ulonglong2 ld2(const float* p) {
    return *reinterpret_cast<const ulonglong2*>(p);
}
// constant-bank float4 -> 2 packed pairs
__device__ __forceinline__ void cw2(int idx, u64& p0, u64& p1) {
    float4 v = CW[idx];
    p0 = pk(v.x, v.y);
    p1 = pk(v.z, v.w);
}

// one GINE layer + LN + relu for NV graphs; weights from __constant__.
template<int LWo, int LBo, int W1o, int B1o, int W2o, int B2o>
__device__ __forceinline__ void gineN(
    u64 h[NV][8], int lane, int node,
    const float* __restrict__ ea, const int* gc)
{
    u64 agg[NV][8];
#pragma unroll
    for (int nv = 0; nv < NV; nv++)
#pragma unroll
        for (int j = 0; j < 8; j++) agg[nv][j] = 0ull;

    // ---- message stage: weights hoisted across all 3 neighbors ----
    float ef[NV][3][4];
    int slv[3];
#pragma unroll
    for (int m = 1; m < 4; m++) {
        int src = (node + m) & 3;
        int eidx = src * 3 + node - (node > src ? 1 : 0);
        slv[m - 1] = (lane & ~3) | src;
#pragma unroll
        for (int nv = 0; nv < NV; nv++) {
            float4 e = __ldg(reinterpret_cast<const float4*>(
                ea + (long long)gc[nv] * 48 + eidx * 4));
            ef[nv][m-1][0] = e.x; ef[nv][m-1][1] = e.y;
            ef[nv][m-1][2] = e.z; ef[nv][m-1][3] = e.w;
        }
    }

#pragma unroll
    for (int v = 0; v < 4; v++) {           // chunk: dim-pairs 2v, 2v+1
        u64 msg[NV][3][2];
        {
            u64 b0, b1; cw2(LBo + v, b0, b1);
#pragma unroll
            for (int nv = 0; nv < NV; nv++)
#pragma unroll
                for (int mm = 0; mm < 3; mm++) {
                    msg[nv][mm][0] = b0; msg[nv][mm][1] = b1;
                }
        }
#pragma unroll
        for (int k = 0; k < 4; k++) {
            u64 w0, w1; cw2(LWo + k * 4 + v, w0, w1);
#pragma unroll
            for (int mm = 0; mm < 3; mm++)
#pragma unroll
                for (int nv = 0; nv < NV; nv++) {
                    u64 ep = pk(ef[nv][mm][k], ef[nv][mm][k]);
                    msg[nv][mm][0] = f2(ep, w0, msg[nv][mm][0]);
                    msg[nv][mm][1] = f2(ep, w1, msg[nv][mm][1]);
                }
        }
#pragma unroll
        for (int mm = 0; mm < 3; mm++) {
            int sl = slv[mm];
#pragma unroll
            for (int nv = 0; nv < NV; nv++)
#pragma unroll
                for (int pr = 0; pr < 2; pr++) {
                    int j = 2 * v + pr;
                    u64 hs = __shfl_sync(0xffffffffu, h[nv][j], sl);
                    agg[nv][j] = a2(agg[nv][j], r2(a2(msg[nv][mm][pr], hs)));
                }
        }
    }

    // in-place: h becomes the MLP input (h + agg)
#pragma unroll
    for (int nv = 0; nv < NV; nv++)
#pragma unroll
        for (int j = 0; j < 8; j++) h[nv][j] = a2(h[nv][j], agg[nv][j]);

    u64 out[NV][8];
    {
        u64 b[8];
        cw2(B2o + 0, b[0], b[1]); cw2(B2o + 1, b[2], b[3]);
        cw2(B2o + 2, b[4], b[5]); cw2(B2o + 3, b[6], b[7]);
#pragma unroll
        for (int nv = 0; nv < NV; nv++)
#pragma unroll
            for (int j = 0; j < 8; j++) out[nv][j] = b[j];
    }

    // 8 chunks of 8 hidden units (4 pairs each)
#pragma unroll
    for (int c = 0; c < 8; c++) {
        u64 hid[NV][4];
        {
            u64 b0, b1, b2v, b3;
            cw2(B1o + 2 * c, b0, b1);
            cw2(B1o + 2 * c + 1, b2v, b3);
#pragma unroll
            for (int nv = 0; nv < NV; nv++) {
                hid[nv][0] = b0; hid[nv][1] = b1; hid[nv][2] = b2v; hid[nv][3] = b3;
            }
        }
#pragma unroll
        for (int jp = 0; jp < 8; jp++) {
            u64 xlo[NV], xhi[NV];
#pragma unroll
            for (int nv = 0; nv < NV; nv++) {
                float a, b; up(h[nv][jp], a, b);
                xlo[nv] = pk(a, a); xhi[nv] = pk(b, b);
            }
#pragma unroll
            for (int t = 0; t < 2; t++) {
                int k = 2 * jp + t;
                u64 wv[4];
                cw2(W1o + k * 16 + 2 * c, wv[0], wv[1]);
                cw2(W1o + k * 16 + 2 * c + 1, wv[2], wv[3]);
#pragma unroll
                for (int nv = 0; nv < NV; nv++) {
                    u64 xp = t ? xhi[nv] : xlo[nv];
#pragma unroll
                    for (int v = 0; v < 4; v++)
                        hid[nv][v] = f2(xp, wv[v], hid[nv][v]);
                }
            }
        }
        // relu + second matmul
#pragma unroll
        for (int v = 0; v < 4; v++) {
            float s0[NV], s1[NV];
#pragma unroll
            for (int nv = 0; nv < NV; nv++) {
                float a, b; up(hid[nv][v], a, b);
                s0[nv] = fmaxf(a, 0.f); s1[nv] = fmaxf(b, 0.f);
            }
#pragma unroll
            for (int t = 0; t < 2; t++) {
                int u = c * 8 + 2 * v + t;
                u64 wv[8];
                cw2(W2o + u * 4 + 0, wv[0], wv[1]);
                cw2(W2o + u * 4 + 1, wv[2], wv[3]);
                cw2(W2o + u * 4 + 2, wv[4], wv[5]);
                cw2(W2o + u * 4 + 3, wv[6], wv[7]);
#pragma unroll
                for (int nv = 0; nv < NV; nv++) {
                    float s = t ? s1[nv] : s0[nv];
                    u64 sp = pk(s, s);
#pragma unroll
                    for (int jj = 0; jj < 8; jj++)
                        out[nv][jj] = f2(sp, wv[jj], out[nv][jj]);
                }
            }
        }
    }

    // LayerNorm (ddof=0) + relu -> back into packed h
#pragma unroll
    for (int nv = 0; nv < NV; nv++) {
        float o[16];
#pragma unroll
        for (int j = 0; j < 8; j++) up(out[nv][j], o[2*j], o[2*j+1]);
        float mean = 0.f;
#pragma unroll
        for (int d = 0; d < 16; d++) mean += o[d];
        mean *= (1.f / 16.f);
        float var = 0.f;
#pragma unroll
        for (int d = 0; d < 16; d++) { float dd = o[d] - mean; var = fmaf(dd, dd, var); }
        var *= (1.f / 16.f);
        float inv = rsqrtf(var + 1e-5f);
#pragma unroll
        for (int j = 0; j < 8; j++)
            h[nv][j] = pk(fmaxf((o[2*j] - mean) * inv, 0.f),
                          fmaxf((o[2*j+1] - mean) * inv, 0.f));
    }
}

__global__ void __launch_bounds__(NTHREADS, 2)
gnn_kernel(Params p)
{
    __shared__ float S[SMEM_FLOATS];

    // stage encoder + FC weights into shared
    {
        const int map[11]   = {0,1,2,3,4,5,6,7, 20,21,22};
        const int sizes[11] = {80,16,256,16, 80,16,256,16, 2048,64,64};
        const int offs[11]  = {JE_W1,JE_B1,JE_W2,JE_B2, MU_W1,MU_B1,MU_W2,MU_B2,
                               FC_W1,FC_B1,FC_W2};
        for (int a = 0; a < 11; a++) {
            const float* src = p.w[map[a]];
            float* dst = S + offs[a];
            int n = sizes[a];
            for (int i = threadIdx.x; i < n; i += NTHREADS) dst[i] = src[i];
        }
    }
    __syncthreads();

    int tid = threadIdx.x;
    int lane = tid & 31;
    int node = lane & 3;
    int group = lane >> 2;
    int warpG = (int)((blockIdx.x * (unsigned)NTHREADS + tid) >> 5);

    if (warpG * 16 >= p.G) return;   // warp-uniform

    int base = warpG * 16 + group;
    int gidx[NV], gc[NV];
    bool valid[NV];
#pragma unroll
    for (int nv = 0; nv < NV; nv++) {
        gidx[nv] = base + 8 * nv;
        valid[nv] = gidx[nv] < p.G;
        gc[nv] = valid[nv] ? gidx[nv] : (p.G - 1);
    }

    // ---- heterogeneous encoder (shared, node-divergent base) ----
    const float* w1p = (node == 3) ? (S + MU_W1) : (S + JE_W1);
    const float* b1p = (node == 3) ? (S + MU_B1) : (S + JE_B1);
    const float* w2p = (node == 3) ? (S + MU_W2) : (S + JE_W2);
    const float* b2p = (node == 3) ? (S + MU_B2) : (S + JE_B2);

    u64 h[NV][8];
    {
        float xin[NV][5];
#pragma unroll
        for (int nv = 0; nv < NV; nv++) {
            const float* xr = p.x + (long long)(gc[nv] * 4 + node) * 5;
#pragma unroll
            for (int k = 0; k < 5; k++) xin[nv][k] = __ldg(xr + k);
        }

        u64 tv[NV][8];
        {
            ulonglong2 a = ld2(b1p), b = ld2(b1p+4), c = ld2(b1p+8), d = ld2(b1p+12);
#pragma unroll
            for (int nv = 0; nv < NV; nv++) {
                tv[nv][0]=a.x; tv[nv][1]=a.y; tv[nv][2]=b.x; tv[nv][3]=b.y;
                tv[nv][4]=c.x; tv[nv][5]=c.y; tv[nv][6]=d.x; tv[nv][7]=d.y;
            }
        }
#pragma unroll
        for (int k = 0; k < 5; k++) {
            const float* r = w1p + k * 16;
            ulonglong2 wa = ld2(r), wb = ld2(r+4), wc = ld2(r+8), wd = ld2(r+12);
            u64 wv[8] = {wa.x,wa.y,wb.x,wb.y,wc.x,wc.y,wd.x,wd.y};
#pragma unroll
            for (int nv = 0; nv < NV; nv++) {
                u64 xp = pk(xin[nv][k], xin[nv][k]);
#pragma unroll
                for (int j = 0; j < 8; j++)
                    tv[nv][j] = f2(xp, wv[j], tv[nv][j]);
            }
        }

        {
            ulonglong2 a = ld2(b2p), b = ld2(b2p+4), c = ld2(b2p+8), d = ld2(b2p+12);
#pragma unroll
            for (int nv = 0; nv < NV; nv++) {
                h[nv][0]=a.x; h[nv][1]=a.y; h[nv][2]=b.x; h[nv][3]=b.y;
                h[nv][4]=c.x; h[nv][5]=c.y; h[nv][6]=d.x; h[nv][7]=d.y;
            }
        }
#pragma unroll
        for (int jp = 0; jp < 8; jp++) {
            u64 xlo[NV], xhi[NV];
#pragma unroll
            for (int nv = 0; nv < NV; nv++) {
                float a, b; up(tv[nv][jp], a, b);
                xlo[nv] = pk(fmaxf(a, 0.f), fmaxf(a, 0.f));
                xhi[nv] = pk(fmaxf(b, 0.f), fmaxf(b, 0.f));
            }
#pragma unroll
            for (int t = 0; t < 2; t++) {
                const float* r = w2p + (2 * jp + t) * 16;
                ulonglong2 wa = ld2(r), wb = ld2(r+4), wc = ld2(r+8), wd = ld2(r+12);
                u64 wv[8] = {wa.x,wa.y,wb.x,wb.y,wc.x,wc.y,wd.x,wd.y};
#pragma unroll
                for (int nv = 0; nv < NV; nv++) {
                    u64 xp = t ? xhi[nv] : xlo[nv];
#pragma unroll
                    for (int j = 0; j < 8; j++)
                        h[nv][j] = f2(xp, wv[j], h[nv][j]);
                }
            }
        }
    }

    // ---- two GINE blocks (constant-memory weights) ----
    gineN<cL1W, cL1B, cM1W1, cM1B1, cM1W2, cM1B2>(h, lane, node, p.ea, gc);
    gineN<cL2W, cL2B, cM2W1, cM2B1, cM2W2, cM2B2>(h, lane, node, p.ea, gc);

    // ---- pooling (mean + max over the 4 lanes of the graph, packed shfl) + LN ----
    float g[NV][32];
#pragma unroll
    for (int nv = 0; nv < NV; nv++) {
#pragma unroll
        for (int j = 0; j < 8; j++) {
            u64 s = h[nv][j];
            s = a2(s, __shfl_xor_sync(0xffffffffu, s, 1));
            s = a2(s, __shfl_xor_sync(0xffffffffu, s, 2));
            float sa, sb; up(s, sa, sb);
            g[nv][2*j]   = sa * 0.25f;
            g[nv][2*j+1] = sb * 0.25f;

            u64 mx = h[nv][j];
            u64 o1 = __shfl_xor_sync(0xffffffffu, mx, 1);
            float a0, b0, a1, b1; up(mx, a0, b0); up(o1, a1, b1);
            mx = pk(fmaxf(a0, a1), fmaxf(b0, b1));
            u64 o2 = __shfl_xor_sync(0xffffffffu, mx, 2);
            up(mx, a0, b0); up(o2, a1, b1);
            g[nv][16 + 2*j]   = fmaxf(a0, a1);
            g[nv][16 + 2*j+1] = fmaxf(b0, b1);
        }
        float mean = 0.f;
#pragma unroll
        for (int d = 0; d < 32; d++) mean += g[nv][d];
        mean *= (1.f / 32.f);
        float var = 0.f;
#pragma unroll
        for (int d = 0; d < 32; d++) { float dd = g[nv][d] - mean; var = fmaf(dd, dd, var); }
        var *= (1.f / 32.f);
        float inv = rsqrtf(var + 1e-5f);
#pragma unroll
        for (int d = 0; d < 32; d++) g[nv][d] = (g[nv][d] - mean) * inv;
    }

    // ---- FC head: 32 -> 64 -> 1; node-divergent slices from shared ----
    u64 av[NV][8];
    {
        const float* r = S + FC_B1 + node * 16;
        ulonglong2 a = ld2(r), b = ld2(r+4), c = ld2(r+8), d = ld2(r+12);
#pragma unroll
        for (int nv = 0; nv < NV; nv++) {
            av[nv][0]=a.x; av[nv][1]=a.y; av[nv][2]=b.x; av[nv][3]=b.y;
            av[nv][4]=c.x; av[nv][5]=c.y; av[nv][6]=d.x; av[nv][7]=d.y;
        }
    }
#pragma unroll
    for (int k = 0; k < 32; k++) {
        const float* r = S + FC_W1 + k * 64 + node * 16;
        ulonglong2 wa = ld2(r), wb = ld2(r+4), wc = ld2(r+8), wd = ld2(r+12);
        u64 wv[8] = {wa.x,wa.y,wb.x,wb.y,wc.x,wc.y,wd.x,wd.y};
#pragma unroll
        for (int nv = 0; nv < NV; nv++) {
            u64 gp = pk(g[nv][k], g[nv][k]);
#pragma unroll
            for (int j = 0; j < 8; j++) av[nv][j] = f2(gp, wv[j], av[nv][j]);
        }
    }
    float acc[NV] = {0.f, 0.f};
#pragma unroll
    for (int j = 0; j < 8; j++) {
        float2 w2v = *reinterpret_cast<const float2*>(S + FC_W2 + node * 16 + 2 * j);
#pragma unroll
        for (int nv = 0; nv < NV; nv++) {
            float a, b; up(av[nv][j], a, b);
            acc[nv] = fmaf(fmaxf(a, 0.f), w2v.x, acc[nv]);
            acc[nv] = fmaf(fmaxf(b, 0.f), w2v.y, acc[nv]);
        }
    }
    const float fcb2 = __ldg(p.w[23]);
#pragma unroll
    for (int nv = 0; nv < NV; nv++) {
        acc[nv] += __shfl_xor_sync(0xffffffffu, acc[nv], 1);
        acc[nv] += __shfl_xor_sync(0xffffffffu, acc[nv], 2);
        if (node == 0 && valid[nv])
            p.out[gidx[nv]] = acc[nv] + fcb2;
    }
}

extern "C" void kernel_launch(void* const* d_in, const int* in_sizes, int n_in,
                              void* d_out, int out_size)
{
    Params p;
    p.x  = (const float*)d_in[0];
    p.ea = (const float*)d_in[1];
    for (int i = 0; i < 24; i++) p.w[i] = (const float*)d_in[2 + i];
    p.out = (float*)d_out;
    p.G = in_sizes[0] / 20;            // x is [G*4, 5]

    // Fill constant bank by writing through its global-space address.
    // Identical values every replay -> any stale const-cache line is benign.
    void* cw_addr = nullptr;
    cudaGetSymbolAddress(&cw_addr, CW);
    PackP pp;
    for (int i = 0; i < 12; i++) pp.src[i] = (const float*)d_in[10 + i]; // lin1..m2_b2
    pp.dst = (float*)cw_addr;
    pack_kernel<<<1, 256>>>(pp);

    // 16 graphs per warp, 8 warps per block -> 128 graphs per block
    int blocks = (p.G + 127) / 128;
    if (blocks < 1) blocks = 1;
    gnn_kernel<<<blocks, NTHREADS>>>(p);
}